// round 14
// baseline (speedup 1.0000x reference)
#include <cuda_runtime.h>

// GraphPyramidPooling — adjacency (d_in[0]) is dead code. Live math:
//   s0 = sig(h·w0+b0); s1 = sig(s0*(h·w1)+b1); s2 = sig((s0*s1)*(h·w2)+b2)
//   out[r] = a0[r]*h[r] + g1[r]*h[src1[r]] + g2[r]*h[src2[r]]
//
// R13: 3 launches (R12 structure). megarank's radix-select histograms now
// use warp-aggregated ballot counting (1 atomic per distinct digit per warp)
// instead of per-key smem atomics — sigmoid keys concentrate in ~2 top-byte
// bins, which serialized R12's ATOMS (~17us). s2 staged in smem too (64KB).

typedef unsigned long long u64;
typedef unsigned int u32;

#define D   512
#define DV  128
#define N0  4096
#define KS0 3276
#define KS1 1965
#define KS2 786

#define MNB 128
#define MNT 1024
#define SMEM_BYTES (N0 * 8 + N0 * 4 + N0 * 4)   // 64KB

__device__ u64   g_k0[N0];
__device__ u32   g_s1b[N0];
__device__ u32   g_s2b[N0];
__device__ float g_a0[N0];
__device__ float g_g1[KS0];
__device__ int   g_src1[KS0];
__device__ float g_gain2[KS1];
__device__ int   g_src2[KS1];

__device__ __forceinline__ float warp_sum(float v) {
#pragma unroll
    for (int o = 16; o; o >>= 1) v += __shfl_xor_sync(0xffffffffu, v, o);
    return v;
}
__device__ __forceinline__ float sigmoidf(float x) {
    return 1.0f / (1.0f + expf(-x));
}

// K1: one warp per row; 3 dots; all three per-row scores (verified).
__global__ void pass_a(const float* __restrict__ h,
                       const float* __restrict__ W,
                       const float* __restrict__ b) {
    int w    = (blockIdx.x * blockDim.x + threadIdx.x) >> 5;
    int lane = threadIdx.x & 31;
    if (w >= N0) return;
    const float4* hr = (const float4*)h + (size_t)w * DV;
    const float4* w0 = (const float4*)W;
    const float4* w1 = w0 + DV;
    const float4* w2 = w0 + 2 * DV;
    float a0 = 0.f, a1 = 0.f, a2 = 0.f;
#pragma unroll
    for (int i = 0; i < 4; i++) {
        float4 a  = __ldg(hr + lane + 32 * i);
        float4 c0 = __ldg(w0 + lane + 32 * i);
        float4 c1 = __ldg(w1 + lane + 32 * i);
        float4 c2 = __ldg(w2 + lane + 32 * i);
        a0 += a.x * c0.x + a.y * c0.y + a.z * c0.z + a.w * c0.w;
        a1 += a.x * c1.x + a.y * c1.y + a.z * c1.z + a.w * c1.w;
        a2 += a.x * c2.x + a.y * c2.y + a.z * c2.z + a.w * c2.w;
    }
    a0 = warp_sum(a0); a1 = warp_sum(a1); a2 = warp_sum(a2);
    if (lane == 0) {
        float s0 = sigmoidf(a0 + b[0]);
        float s1 = sigmoidf(s0 * a1 + b[1]);
        float s2 = sigmoidf((s0 * s1) * a2 + b[2]);
        g_k0[w]  = ((u64)(u32)__float_as_int(s0) << 32) | (u32)(~(u32)w);
        g_s1b[w] = (u32)__float_as_int(s1);
        g_s2b[w] = (u32)__float_as_int(s2);
    }
}

// Warp-aggregated histogram add: one atomic per distinct digit per warp.
__device__ __forceinline__ void hist_add(u32* hist, u32 digit, bool valid) {
    const int lane = threadIdx.x & 31;
    u32 active = __ballot_sync(0xffffffffu, valid);
    while (active) {
        int leader = __ffs(active) - 1;
        u32 ldig = __shfl_sync(0xffffffffu, digit, leader);
        u32 match = __ballot_sync(0xffffffffu, valid && digit == ldig) & active;
        if (lane == leader) atomicAdd(&hist[ldig], __popc(match));
        active &= ~match;
    }
}

// Exact MSD radix select over a masked key set (functor f(j,&k) -> valid).
// Returns threshold ROW index when a unique candidate is isolated; else -1
// with out_prefix = duplicated key value, out_res = residual want.
template <class F>
__device__ int radix_sel(F f, int n, int want0, u32* hist, int* ctl, int* s_j,
                         u64& out_prefix, int& out_res) {
    const int tid = threadIdx.x;
    int want = want0;
    u64 prefix = 0, pmask = 0;
    for (int shift = 56; shift >= 0; shift -= 8) {
        if (tid < 256) hist[tid] = 0;
        __syncthreads();
        for (int j = tid; j < n; j += MNT) {
            u64 k;
            bool v = f(j, k) && ((k ^ prefix) & pmask) == 0;
            hist_add(hist, v ? (u32)(k >> shift) & 255 : 0u, v);
        }
        __syncthreads();
        if (tid < 32) {
            u32 hh[8]; u32 lsum = 0;
#pragma unroll
            for (int q = 0; q < 8; q++) { hh[q] = hist[tid * 8 + q]; lsum += hh[q]; }
            u32 suf = lsum;
#pragma unroll
            for (int o = 1; o < 32; o <<= 1) {
                u32 v = __shfl_down_sync(0xffffffffu, suf, o);
                if (tid + o < 32) suf += v;
            }
            u32 run = suf - lsum;   // keys with digit strictly above this lane
            for (int q = 7; q >= 0; q--) {
                u32 ge = run + hh[q];
                if ((int)run < want && want <= (int)ge) {
                    ctl[0] = tid * 8 + q;
                    ctl[1] = want - (int)run;
                    ctl[2] = (int)hh[q];
                }
                run = ge;
            }
        }
        __syncthreads();
        const int bin = ctl[0];
        const int cnt = ctl[2];
        want = ctl[1];
        prefix |= ((u64)(u32)bin) << shift;
        pmask  |= 255ULL << shift;
        __syncthreads();
        if (cnt == 1) {
            for (int j = tid; j < n; j += MNT) {
                u64 k;
                if (f(j, k) && ((k ^ prefix) & pmask) == 0) *s_j = j;
            }
            __syncthreads();
            return *s_j;
        }
    }
    out_prefix = prefix;
    out_res = want;
    return -1;
}

// K2: thresholds + fused rank0/rank1 scan + scatter (structure verified R12).
__global__ void __launch_bounds__(MNT) megarank() {
    extern __shared__ __align__(16) u64 sh[];
    u64* K0s = sh;                       // 4096 u64 (32KB)
    u32* S1s = (u32*)(sh + N0);          // 4096 u32 (16KB)
    u32* S2s = S1s + N0;                 // 4096 u32 (16KB)
    __shared__ u32 hist[256];
    __shared__ int ctl[3];
    __shared__ int s_j;

    const int tid = threadIdx.x;
    for (int t = tid; t < N0 / 2; t += MNT)
        ((ulonglong2*)K0s)[t] = __ldg((const ulonglong2*)g_k0 + t);
    for (int t = tid; t < N0 / 4; t += MNT) {
        ((uint4*)S1s)[t] = __ldg((const uint4*)g_s1b + t);
        ((uint4*)S2s)[t] = __ldg((const uint4*)g_s2b + t);
    }
    __syncthreads();

    u64 dp; int dr;

    // ---- T0: KS0-th largest k0 (unique -> exact) ----
    auto f0 = [&](int j, u64& k) { k = K0s[j]; return true; };
    const int j0 = radix_sel(f0, N0, KS0, hist, ctl, &s_j, dp, dr);
    const u64 T0 = K0s[j0];

    // ---- T1: KS1-th largest lex(s1, k0) among {k0 >= T0} ----
    auto f1a = [&](int j, u64& k) {
        u64 kk = K0s[j];
        if (kk < T0) return false;
        k = ((u64)S1s[j] << 32) | (kk >> 32);   // (s1, s0)
        return true;
    };
    u64 p1 = 0; int w1 = 0;
    int j1 = radix_sel(f1a, N0, KS1, hist, ctl, &s_j, p1, w1);
    if (j1 < 0) {   // (s1,s0) duplicates: break by ~i (low 32 of k0, unique)
        auto f1b = [&](int j, u64& k) {
            u64 kk = K0s[j];
            if (kk < T0) return false;
            if (((((u64)S1s[j]) << 32) | (kk >> 32)) != p1) return false;
            k = (u64)(u32)kk;
            return true;
        };
        j1 = radix_sel(f1b, N0, w1, hist, ctl, &s_j, dp, dr);
    }
    const u32 T1s1 = S1s[j1];
    const u64 T1k0 = K0s[j1];

    // ---- T2: KS2-th largest lex(s2, s1, k0) among mask1 ----
    auto m1f = [&](int j) {
        u64 kk = K0s[j];
        if (kk < T0) return false;
        u32 s1 = S1s[j];
        return (s1 > T1s1) || (s1 == T1s1 && kk >= T1k0);
    };
    auto f2a = [&](int j, u64& k) {
        if (!m1f(j)) return false;
        k = ((u64)S2s[j] << 32) | S1s[j];   // (s2, s1)
        return true;
    };
    u64 p2 = 0; int w2 = 0;
    int j2 = radix_sel(f2a, N0, KS2, hist, ctl, &s_j, p2, w2);
    if (j2 < 0) {   // (s2,s1) duplicates: break by full k0 (unique)
        auto f2b = [&](int j, u64& k) {
            if (!m1f(j)) return false;
            if ((((u64)S2s[j] << 32) | S1s[j]) != p2) return false;
            k = K0s[j];
            return true;
        };
        j2 = radix_sel(f2b, N0, w2, hist, ctl, &s_j, dp, dr);
    }
    const u32 T2s2 = S2s[j2];
    const u32 T2s1 = S1s[j2];
    const u64 T2k0 = K0s[j2];

    // ---- fused scan: rank0 (k0 desc) + rank1 (lex(s1,k0) desc among m0) ----
    const int wid  = tid >> 5;
    const int lane = tid & 31;
    const int i = blockIdx.x * 32 + wid;   // 128*32 = 4096
    const u64 kI = K0s[i];
    const u32 sI = S1s[i];
    int c0 = 0, c1 = 0;
    const ulonglong2* K2p = (const ulonglong2*)K0s;
    const uint2*      S2q = (const uint2*)S1s;
#pragma unroll 4
    for (int q = lane; q < N0 / 2; q += 32) {
        ulonglong2 kv = K2p[q];
        uint2      sv = S2q[q];
        int g0x = (int)(kv.x > kI), g0y = (int)(kv.y > kI);
        int l1x = (int)(sv.x > sI) | ((int)(sv.x == sI) & g0x);
        int l1y = (int)(sv.y > sI) | ((int)(sv.y == sI) & g0y);
        c0 += g0x + g0y;
        c1 += ((int)(kv.x >= T0) & l1x) + ((int)(kv.y >= T0) & l1y);
    }
    int p = c0 | (c1 << 16);
#pragma unroll
    for (int o = 16; o; o >>= 1) p += __shfl_xor_sync(0xffffffffu, p, o);

    if (lane == 0) {
        const int rank0 = p & 0xFFFF;
        const int rank1 = p >> 16;
        const float s0 = __uint_as_float((int)(u32)(kI >> 32));
        const bool sel0 = kI >= T0;   // == (rank0 < KS0), exact
        g_a0[i] = sel0 ? s0 : 0.f;
        if (sel0) {
            const float s1 = __uint_as_float((int)sI);
            const float gain1 = s0 * s1;
            const bool m1i = (sI > T1s1) || (sI == T1s1 && kI >= T1k0);
            g_g1[rank0]   = m1i ? gain1 : 0.f;
            g_src1[rank0] = i;
            if (m1i) {
                const u32 s2b = S2s[i];
                const bool sel2 = (s2b > T2s2) ||
                    (s2b == T2s2 && (sI > T2s1 ||
                                     (sI == T2s1 && kI >= T2k0)));
                g_gain2[rank1] = sel2 ? gain1 * __uint_as_float((int)s2b) : 0.f;
                g_src2[rank1]  = i;
            }
        }
    }
}

// K3: out[r] = a0*h[r] + g1*h[src1] + g2*h[src2] (verified gather).
__global__ void __launch_bounds__(512)
final_kernel(const float* __restrict__ h, float* __restrict__ out) {
    int tid = blockIdx.x * 512 + threadIdx.x;   // 0 .. N0*DV-1
    int r = tid >> 7;
    int c = tid & 127;
    const float4* h4 = (const float4*)h;
    float a0 = __ldg(g_a0 + r);
    float4 v0 = __ldg(h4 + (size_t)r * DV + c);
    float4 o;
    o.x = a0 * v0.x; o.y = a0 * v0.y; o.z = a0 * v0.z; o.w = a0 * v0.w;
    if (r < KS0) {
        float g1 = __ldg(g_g1 + r);
        int   s1 = __ldg(g_src1 + r);
        float4 v1 = __ldg(h4 + (size_t)s1 * DV + c);
        o.x += g1 * v1.x; o.y += g1 * v1.y; o.z += g1 * v1.z; o.w += g1 * v1.w;
        if (r < KS1) {
            float g2 = __ldg(g_gain2 + r);
            int   s2 = __ldg(g_src2 + r);
            float4 v2 = __ldg(h4 + (size_t)s2 * DV + c);
            o.x += g2 * v2.x; o.y += g2 * v2.y; o.z += g2 * v2.z; o.w += g2 * v2.w;
        }
    }
    ((float4*)out)[tid] = o;
}

extern "C" void kernel_launch(void* const* d_in, const int* in_sizes, int n_in,
                              void* d_out, int out_size) {
    // inputs: [0]=g (UNUSED), [1]=h [4096,512], [2]=W [3,512], [3]=b [3]
    const float* h = (const float*)d_in[1];
    const float* W = (const float*)d_in[2];
    const float* b = (const float*)d_in[3];
    float* out = (float*)d_out;

    cudaFuncSetAttribute(megarank,
                         cudaFuncAttributeMaxDynamicSharedMemorySize,
                         SMEM_BYTES);
    pass_a<<<N0 / 8, 256>>>(h, W, b);
    megarank<<<MNB, MNT, SMEM_BYTES>>>();
    final_kernel<<<(N0 * DV) / 512, 512>>>(h, out);
}

// round 16
// speedup vs baseline: 2.0614x; 2.0614x over previous
#include <cuda_runtime.h>

// GraphPyramidPooling — adjacency (d_in[0]) is dead code. Live math:
//   s0 = sig(h·w0+b0); s1 = sig(s0*(h·w1)+b1); s2 = sig((s0*s1)*(h·w2)+b2)
//   out[r] = a0[r]*h[r] + g1[r]*h[src1[r]] + g2[r]*h[src2[r]]
// exact stable top-k via u64 keys (bits(score)<<32 | ~pos).
//
// R15: R14 with the one-line fix — smk2 stages ALL of g_k2lv, so the gather
// must read smk2[r], not smk2[r - row0] (that bug flipped level-2 selection
// for every block but block 0 -> rel_err 0.16). Kept from R14:
//  (1) pass_a at 128 threads/row (full occupancy),
//  (2) T2 radix select with per-warp histograms (no same-address ATOMS).

#define D   512
#define DV  (D/4)
#define N0  4096
#define K0  3276
#define N1  3276
#define K1  1965
#define K2  786
#define NP0 4096
#define NP1 3328

#define RNB 148
#define RNT 512
#define RNW (RNB * 16)   // 2368 warps
#define FNT 512
#define FNB ((N0 * DV / 2) / FNT)   // 512 blocks, 2 float4 per thread

typedef unsigned long long u64;
typedef unsigned int u32;

__device__ u64   g_k0[NP0];
__device__ u64   g_k1[N1];
__device__ u32   g_s2lv[N1];    // s2 bits at level-1 positions
__device__ float g_s0a[N0];
__device__ float g_s1a[N0];
__device__ u32   g_s2a[N0];
__device__ float g_a0[N0];
__device__ float g_g1[K0];
__device__ int   g_src1[K0];
__device__ u64   g_k2lv[K1];    // (s2<<32 | ~rank1) at level-2 positions
__device__ float g_gain2[K1];   // s0*s1*s2 (value if selected)
__device__ int   g_src2[K1];
__device__ int   g_inv0[N1];

__device__ __forceinline__ float warp_sum(float v) {
#pragma unroll
    for (int o = 16; o; o >>= 1) v += __shfl_xor_sync(0xffffffffu, v, o);
    return v;
}
__device__ __forceinline__ float sigmoidf(float x) {
    return 1.0f / (1.0f + expf(-x));
}
__device__ __forceinline__ u64 make_key(float s, int idx) {
    return ((u64)(u32)__float_as_int(s) << 32) | (u32)(~(u32)idx);
}
__device__ __forceinline__ float key_score(u64 k) {
    return __int_as_float((int)(k >> 32));
}

// K1: 128 threads per row (2 rows per 256-thr block, 2048 blocks -> full
// occupancy). Each thread: 1 h float4 + 3 W float4 (broadcast, L1-hot);
// 4-warp smem reduction per row; all three per-row scores.
__global__ void __launch_bounds__(256)
pass_a(const float* __restrict__ h, const float* __restrict__ W,
       const float* __restrict__ b) {
    __shared__ float red[2][4][3];
    const int tid  = threadIdx.x;
    const int rloc = tid >> 7;          // 0..1
    const int col  = tid & 127;         // float4 column
    const int lane = tid & 31;
    const int wq   = (tid >> 5) & 3;    // warp within row-group
    const int row  = blockIdx.x * 2 + rloc;

    const float4* h4 = (const float4*)h;
    const float4* w4 = (const float4*)W;
    float4 a  = __ldg(h4 + (size_t)row * DV + col);
    float4 c0 = __ldg(w4 + col);
    float4 c1 = __ldg(w4 + DV + col);
    float4 c2 = __ldg(w4 + 2 * DV + col);
    float d0 = a.x * c0.x + a.y * c0.y + a.z * c0.z + a.w * c0.w;
    float d1 = a.x * c1.x + a.y * c1.y + a.z * c1.z + a.w * c1.w;
    float d2 = a.x * c2.x + a.y * c2.y + a.z * c2.z + a.w * c2.w;
    d0 = warp_sum(d0); d1 = warp_sum(d1); d2 = warp_sum(d2);
    if (lane == 0) {
        red[rloc][wq][0] = d0;
        red[rloc][wq][1] = d1;
        red[rloc][wq][2] = d2;
    }
    __syncthreads();
    if (col == 0) {
        float a0 = red[rloc][0][0] + red[rloc][1][0] + red[rloc][2][0] + red[rloc][3][0];
        float a1 = red[rloc][0][1] + red[rloc][1][1] + red[rloc][2][1] + red[rloc][3][1];
        float a2 = red[rloc][0][2] + red[rloc][1][2] + red[rloc][2][2] + red[rloc][3][2];
        float s0 = sigmoidf(a0 + b[0]);
        float s1 = sigmoidf(s0 * a1 + b[1]);
        float s2 = sigmoidf((s0 * s1) * a2 + b[2]);
        g_s0a[row] = s0;
        g_s1a[row] = s1;
        g_s2a[row] = (u32)__float_as_int(s2);
        g_k0[row]  = make_key(s0, row);
    }
}

// K2: exact stable rank0; scatter level-1 keys + s2 + inverse map (R11 verbatim).
__global__ void __launch_bounds__(RNT) rank0_kernel() {
    __shared__ __align__(16) u64 smk[NP0];
    for (int t = threadIdx.x; t < NP0 / 2; t += RNT)
        ((ulonglong2*)smk)[t] = __ldg((const ulonglong2*)g_k0 + t);
    __syncthreads();

    const int wid  = threadIdx.x >> 5;
    const int lane = threadIdx.x & 31;
    const int gw   = blockIdx.x * 16 + wid;
    const int i1 = gw, i2 = gw + RNW;

    u64 kA = (i1 < N0) ? smk[i1] : ~0ULL;
    u64 kB = (i2 < N0) ? smk[i2] : ~0ULL;
    int ca = 0, cb = 0;
    const ulonglong2* s2p = (const ulonglong2*)smk;
#pragma unroll 4
    for (int q = lane; q < NP0 / 2; q += 32) {
        ulonglong2 v = s2p[q];
        ca += (int)(v.x > kA) + (int)(v.y > kA);
        cb += (int)(v.x > kB) + (int)(v.y > kB);
    }
    int packed = ca | (cb << 16);
#pragma unroll
    for (int o = 16; o; o >>= 1) packed += __shfl_xor_sync(0xffffffffu, packed, o);
    if (lane != 0) return;

#pragma unroll
    for (int t = 0; t < 2; t++) {
        const int i = (t == 0) ? i1 : i2;
        if (i >= N0) continue;
        const int rank = (t == 0) ? (packed & 0xFFFF) : (packed >> 16);
        const u64 k = (t == 0) ? kA : kB;
        const bool sel = rank < K0;
        float s0 = key_score(k);
        g_a0[i] = sel ? s0 : 0.f;
        if (sel) {
            g_k1[rank]   = make_key(g_s1a[i], rank);
            g_s2lv[rank] = g_s2a[i];
            g_inv0[rank] = i;
        }
    }
}

// K3: exact stable rank1; scatter gains + level-2 keys (R11 verbatim).
__global__ void __launch_bounds__(RNT) rank1_kernel() {
    __shared__ __align__(16) u64 smk[NP1];
    const ulonglong2* gk2 = (const ulonglong2*)g_k1;
    for (int t = threadIdx.x; t < NP1 / 2; t += RNT) {
        ulonglong2 v;
        if (2 * t + 1 < N1) v = __ldg(gk2 + t);
        else { v.x = (2 * t < N1) ? __ldg(g_k1 + 2 * t) : 0ULL; v.y = 0ULL; }
        ((ulonglong2*)smk)[t] = v;
    }
    __syncthreads();

    const int wid  = threadIdx.x >> 5;
    const int lane = threadIdx.x & 31;
    const int gw   = blockIdx.x * 16 + wid;
    const int i1 = gw, i2 = gw + RNW;

    u64 kA = (i1 < N1) ? smk[i1] : ~0ULL;
    u64 kB = (i2 < N1) ? smk[i2] : ~0ULL;
    int ca = 0, cb = 0;
    const ulonglong2* s2p = (const ulonglong2*)smk;
#pragma unroll 4
    for (int q = lane; q < NP1 / 2; q += 32) {
        ulonglong2 v = s2p[q];
        ca += (int)(v.x > kA) + (int)(v.y > kA);
        cb += (int)(v.x > kB) + (int)(v.y > kB);
    }
    int packed = ca | (cb << 16);
#pragma unroll
    for (int o = 16; o; o >>= 1) packed += __shfl_xor_sync(0xffffffffu, packed, o);
    if (lane != 0) return;

#pragma unroll
    for (int t = 0; t < 2; t++) {
        const int p = (t == 0) ? i1 : i2;
        if (p >= N1) continue;
        const int r1 = (t == 0) ? (packed & 0xFFFF) : (packed >> 16);
        const u64 k  = (t == 0) ? kA : kB;
        const bool sel1 = r1 < K1;
        int   src  = g_inv0[p];
        float s1   = key_score(k);
        float gain = g_s0a[src] * s1;
        g_g1[p]   = sel1 ? gain : 0.f;
        g_src1[p] = src;
        if (sel1) {
            float s2 = __uint_as_float((int)g_s2lv[p]);
            g_k2lv[r1]  = make_key(s2, r1);
            g_gain2[r1] = gain * s2;
            g_src2[r1]  = src;
        }
    }
}

// Exact MSD radix select (R11-verified control flow) with PER-WARP histograms.
__device__ u64 select_topk(const u64* keys, int n, int want,
                           u32 (*hist_pw)[256], u32* hist, int* ctl, u64* s_thr) {
    const int tid = threadIdx.x;
    const int wid = tid >> 5;
    u64 prefix = 0, pmask = 0;
    for (int shift = 56; shift >= 0; shift -= 8) {
        for (int t = tid; t < 16 * 256; t += FNT) ((u32*)hist_pw)[t] = 0;
        __syncthreads();
        for (int j = tid; j < n; j += FNT) {
            u64 k = keys[j];
            if (((k ^ prefix) & pmask) == 0)
                atomicAdd(&hist_pw[wid][(u32)(k >> shift) & 255], 1u);
        }
        __syncthreads();
        if (tid < 256) {   // conflict-free combine: lane-indexed banks
            u32 s = 0;
#pragma unroll
            for (int w = 0; w < 16; w++) s += hist_pw[w][tid];
            hist[tid] = s;
        }
        __syncthreads();
        if (tid < 32) {
            u32 hh[8]; u32 lsum = 0;
#pragma unroll
            for (int q = 0; q < 8; q++) { hh[q] = hist[tid * 8 + q]; lsum += hh[q]; }
            u32 suf = lsum;   // inclusive suffix over lanes (hi lane = hi digit)
#pragma unroll
            for (int o = 1; o < 32; o <<= 1) {
                u32 v = __shfl_down_sync(0xffffffffu, suf, o);
                if (tid + o < 32) suf += v;
            }
            u32 run = suf - lsum;
            for (int q = 7; q >= 0; q--) {
                u32 ge = run + hh[q];
                if ((int)run < want && want <= (int)ge) {
                    ctl[0] = tid * 8 + q;
                    ctl[1] = want - (int)run;
                    ctl[2] = (int)hh[q];
                }
                run = ge;
            }
        }
        __syncthreads();
        int bin = ctl[0];
        want    = ctl[1];
        int cnt = ctl[2];
        prefix |= ((u64)(u32)bin) << shift;
        pmask  |= 255ULL << shift;
        if (cnt == 1) {
            for (int j = tid; j < n; j += FNT) {
                u64 k = keys[j];
                if (((k ^ prefix) & pmask) == 0) *s_thr = k;
            }
            __syncthreads();
            return *s_thr;
        }
        __syncthreads();
    }
    return prefix;   // only reachable with duplicate keys (k2lv is unique)
}

// K4: T2 select (blocks owning rows < K1) + gather.
__global__ void __launch_bounds__(FNT)
final_kernel(const float* __restrict__ h, float* __restrict__ out) {
    __shared__ __align__(16) u64 smk2[K1 + 3];
    __shared__ u32 hist_pw[16][256];
    __shared__ u32 hist[256];
    __shared__ int ctl[3];
    __shared__ u64 s_thr;

    const int tid  = threadIdx.x;
    const int row0 = blockIdx.x * (FNT / 64);   // 8 rows per block
    u64 T2 = 0;
    if (row0 < K1) {
        for (int t = tid; t < K1; t += FNT) smk2[t] = __ldg(g_k2lv + t);
        __syncthreads();
        T2 = select_topk(smk2, K1, K2, hist_pw, hist, ctl, &s_thr);
    }

    const int gtid = blockIdx.x * FNT + tid;    // 0 .. N0*DV/2-1
    const int r = gtid >> 6;
    const int c = gtid & 63;
    const float4* h4 = (const float4*)h;
    float a0 = __ldg(g_a0 + r);
    float4 va = __ldg(h4 + (size_t)r * DV + c);
    float4 vb = __ldg(h4 + (size_t)r * DV + c + 64);
    float4 oa, ob;
    oa.x = a0 * va.x; oa.y = a0 * va.y; oa.z = a0 * va.z; oa.w = a0 * va.w;
    ob.x = a0 * vb.x; ob.y = a0 * vb.y; ob.z = a0 * vb.z; ob.w = a0 * vb.w;
    if (r < K0) {
        float g1 = __ldg(g_g1 + r);
        int   s1 = __ldg(g_src1 + r);
        float4 wa = __ldg(h4 + (size_t)s1 * DV + c);
        float4 wb = __ldg(h4 + (size_t)s1 * DV + c + 64);
        oa.x += g1 * wa.x; oa.y += g1 * wa.y; oa.z += g1 * wa.z; oa.w += g1 * wa.w;
        ob.x += g1 * wb.x; ob.y += g1 * wb.y; ob.z += g1 * wb.z; ob.w += g1 * wb.w;
        if (r < K1) {
            u64 k2 = smk2[r];   // FIX: smk2 holds ALL of g_k2lv (was r - row0)
            float g2 = (k2 >= T2) ? __ldg(g_gain2 + r) : 0.f;
            int   s2 = __ldg(g_src2 + r);
            float4 ua = __ldg(h4 + (size_t)s2 * DV + c);
            float4 ub = __ldg(h4 + (size_t)s2 * DV + c + 64);
            oa.x += g2 * ua.x; oa.y += g2 * ua.y; oa.z += g2 * ua.z; oa.w += g2 * ua.w;
            ob.x += g2 * ub.x; ob.y += g2 * ub.y; ob.z += g2 * ub.z; ob.w += g2 * ub.w;
        }
    }
    ((float4*)out)[(size_t)r * DV + c]      = oa;
    ((float4*)out)[(size_t)r * DV + c + 64] = ob;
}

extern "C" void kernel_launch(void* const* d_in, const int* in_sizes, int n_in,
                              void* d_out, int out_size) {
    // inputs: [0]=g (UNUSED), [1]=h [4096,512], [2]=W [3,512], [3]=b [3]
    const float* h = (const float*)d_in[1];
    const float* W = (const float*)d_in[2];
    const float* b = (const float*)d_in[3];
    float* out = (float*)d_out;

    pass_a<<<N0 / 2, 256>>>(h, W, b);
    rank0_kernel<<<RNB, RNT>>>();
    rank1_kernel<<<RNB, RNT>>>();
    final_kernel<<<FNB, FNT>>>(h, out);
}